// round 12
// baseline (speedup 1.0000x reference)
#include <cuda_runtime.h>

// SpectralGatingNetwork: y = irfft2(rfft2(x, ortho) * wc, ortho)
// x: (64, 768, 64, 64) f32; complex_weight: (64, 33, 768, 2) f32; out like x.
//
// Thread-per-line design: CTA = 64 threads, one per row/column of the 64x64
// plane (two channels packed as real/imag). Each 64-pt FFT runs entirely in
// registers (radix-8 x radix-8, compile-time twiddle constants, zero
// shuffles). Direction changes go through one swizzled smem tile. Gate:
// h-partners are in-thread; w-partners live in the adjacent lane (lanes
// 2k/2k+1 own columns k/64-k) and are exchanged with shfl_xor(...,1).
// Ortho norm folded into gate (0.5 Hermitian-split * 1/4096 = 1/8192).

#define CC 768
#define SIG(h) ((((h) & 7) << 3) | ((h) >> 3))

__device__ __forceinline__ float2 cadd(float2 a, float2 b){ return make_float2(a.x+b.x, a.y+b.y); }
__device__ __forceinline__ float2 csub(float2 a, float2 b){ return make_float2(a.x-b.x, a.y-b.y); }
__device__ __forceinline__ float2 cmul(float2 a, float2 b){
    return make_float2(fmaf(a.x, b.x, -a.y*b.y), fmaf(a.x, b.y, a.y*b.x));
}
template<int S>
__device__ __forceinline__ float2 mul_iS(float2 a){
    return (S > 0) ? make_float2(-a.y, a.x) : make_float2(a.y, -a.x);
}

// cos(2*pi*m/64), sin(2*pi*m/64): quarter-wave table, folded at compile time
// (m is always a constant after unrolling).
__device__ __forceinline__ float cos64f(int m){
    constexpr float Q[17] = {
        1.0f, 0.99518472667f, 0.98078528040f, 0.95694033573f,
        0.92387953251f, 0.88192126435f, 0.83146961230f, 0.77301045336f,
        0.70710678119f, 0.63439328416f, 0.55557023302f, 0.47139673683f,
        0.38268343236f, 0.29028467725f, 0.19509032202f, 0.09801714033f, 0.0f };
    m &= 63;
    return (m <= 16) ? Q[m] : (m <= 32) ? -Q[32-m] : (m <= 48) ? -Q[m-32] : Q[64-m];
}
__device__ __forceinline__ float sin64f(int m){ return cos64f(m - 16); }

// 8-point DFT on v[B], v[B+ST], ..., v[B+7*ST] (indices compile-time).
template<int S>
__device__ __forceinline__ void dft8s(float2* v, const int B, const int ST){
    const float r  = 0.70710678118654752440f;
    const float sf = (float)S;
    float2 a0=v[B], a1=v[B+ST], a2=v[B+2*ST], a3=v[B+3*ST],
           a4=v[B+4*ST], a5=v[B+5*ST], a6=v[B+6*ST], a7=v[B+7*ST];
    float2 e0 = cadd(a0, a4), e1 = csub(a0, a4);
    float2 e2 = cadd(a2, a6), e3 = mul_iS<S>(csub(a2, a6));
    float2 E0 = cadd(e0, e2), E2 = csub(e0, e2);
    float2 E1 = cadd(e1, e3), E3 = csub(e1, e3);
    float2 o0 = cadd(a1, a5), o1 = csub(a1, a5);
    float2 o2 = cadd(a3, a7), o3 = mul_iS<S>(csub(a3, a7));
    float2 O0 = cadd(o0, o2), O2 = csub(o0, o2);
    float2 O1 = cadd(o1, o3), O3 = csub(o1, o3);
    float2 t1 = make_float2(r * (O1.x - sf * O1.y), r * (O1.y + sf * O1.x));
    float2 t2 = mul_iS<S>(O2);
    float2 t3 = make_float2(-r * (O3.x + sf * O3.y), r * (sf * O3.x - O3.y));
    v[B]      = cadd(E0, O0); v[B+4*ST] = csub(E0, O0);
    v[B+ST]   = cadd(E1, t1); v[B+5*ST] = csub(E1, t1);
    v[B+2*ST] = cadd(E2, t2); v[B+6*ST] = csub(E2, t2);
    v[B+3*ST] = cadd(E3, t3); v[B+7*ST] = csub(E3, t3);
}

// 64-pt DFT, natural-order input v[n]; output X[k] at slot SIG(k).
template<int S>
__device__ __forceinline__ void fft64r(float2* v){
    #pragma unroll
    for (int n1 = 0; n1 < 8; ++n1) dft8s<S>(v, n1, 8);
    #pragma unroll
    for (int n1 = 1; n1 < 8; ++n1){
        #pragma unroll
        for (int k2 = 1; k2 < 8; ++k2){
            const int p = n1 * k2;
            const float2 w = make_float2(cos64f(p), (S > 0) ? sin64f(p) : -sin64f(p));
            v[n1 + 8*k2] = cmul(v[n1 + 8*k2], w);
        }
    }
    #pragma unroll
    for (int k2 = 0; k2 < 8; ++k2) dft8s<S>(v, 8*k2, 1);
}

// Inverse 64-pt DFT consuming digit-swapped input (u[SIG(k)] = X[k]),
// producing natural-order output (unnormalized).
__device__ __forceinline__ void ifft64ds(float2* v){
    #pragma unroll
    for (int k2 = 0; k2 < 8; ++k2) dft8s<1>(v, 8*k2, 1);
    #pragma unroll
    for (int n1 = 1; n1 < 8; ++n1){
        #pragma unroll
        for (int k2 = 1; k2 < 8; ++k2){
            const int p = n1 * k2;
            const float2 w = make_float2(cos64f(p), sin64f(p));
            v[n1 + 8*k2] = cmul(v[n1 + 8*k2], w);
        }
    }
    #pragma unroll
    for (int n1 = 0; n1 < 8; ++n1) dft8s<1>(v, n1, 8);
}

// Which lane owns spectral column w in Phase B (for swizzle keying).
__device__ __forceinline__ int ownerLane(int w){
    return (w == 0) ? 0 : (w == 32) ? 1 : (w < 32) ? 2*w : 2*(64 - w) + 1;
}

// Hermitian-split gate. Z1 = canonical-point value, Z2 = its partner.
__device__ __forceinline__ float2 gate1(float2 Z1, float2 Z2, float2 Ga, float2 Gb){
    const float sc = 1.0f / 8192.0f;
    const float2 A  = make_float2(sc*(Z1.x + Z2.x), sc*(Z1.y - Z2.y));
    const float2 Bv = make_float2(sc*(Z1.y + Z2.y), sc*(Z2.x - Z1.x));
    const float2 P = cmul(A, Ga), Q = cmul(Bv, Gb);
    return make_float2(P.x - Q.y, P.y + Q.x);           // output at canonical point
}
__device__ __forceinline__ float2 gate2(float2 Z1, float2 Z2, float2 Ga, float2 Gb){
    const float sc = 1.0f / 8192.0f;
    const float2 A  = make_float2(sc*(Z1.x + Z2.x), sc*(Z1.y - Z2.y));
    const float2 Bv = make_float2(sc*(Z1.y + Z2.y), sc*(Z2.x - Z1.x));
    const float2 P = cmul(A, Ga), Q = cmul(Bv, Gb);
    return make_float2(P.x + Q.y, Q.x - P.y);           // output at partner point
}

__global__ void __launch_bounds__(64)
sgn_kernel(const float* __restrict__ x, const float* __restrict__ cw,
           float* __restrict__ out){
    __shared__ __align__(16) float2 tile[64 * 64];

    const int L  = threadIdx.x;        // 0..63
    const int c0 = blockIdx.x * 2;
    const int b  = blockIdx.y;

    const float4* xa4 = (const float4*)(x + ((size_t)(b * CC + c0)) * 4096);
    const float4* xb4 = xa4 + 1024;

    float2 v[64];

    // ---- Phase A: forward row FFT (thread L = row L), gmem -> regs -> smem ----
    #pragma unroll
    for (int m = 0; m < 16; ++m){
        const float4 a  = xa4[L * 16 + m];
        const float4 bb = xb4[L * 16 + m];
        v[4*m+0] = make_float2(a.x, bb.x);
        v[4*m+1] = make_float2(a.y, bb.y);
        v[4*m+2] = make_float2(a.z, bb.z);
        v[4*m+3] = make_float2(a.w, bb.w);
    }
    fft64r<-1>(v);
    {   // store X[w] to tile_T[w][.], h-position permuted (f4 granularity) by
        // q(w) = ownerLane(w)&31 so the column-owner's LDS.128 is conflict-free.
        const int mh = L >> 1, lb = L & 1;
        #pragma unroll
        for (int w = 0; w < 64; ++w){
            const int q = ownerLane(w) & 31;
            tile[w * 64 + (((mh ^ q) << 1) | lb)] = v[SIG(w)];
        }
    }
    __syncthreads();

    // ---- Phase B: load column, fwd FFT, gate, inv FFT, store ----
    const int k   = L >> 1;
    const int od  = L & 1;
    const int col = (k == 0) ? (od ? 32 : 0) : (od ? 64 - k : k);
    {
        const float4* t4 = (const float4*)tile;
        const int base = col * 32, q = L & 31;
        #pragma unroll
        for (int m = 0; m < 32; ++m){
            const float4 f = t4[base + (m ^ q)];
            v[2*m]   = make_float2(f.x, f.y);
            v[2*m+1] = make_float2(f.z, f.w);
        }
    }
    __syncthreads();   // all tile_T reads done before tile_N writes below
    fft64r<-1>(v);     // spectrum Z(h, col) at slot SIG(h)

    const float* cwb = cw + (size_t)c0 * 2;

    // paired rows H=1..31 (partners Hb=64-H); lanes 0,1 are the self-columns
    #pragma unroll
    for (int H = 1; H < 32; ++H){
        const int Hb = 64 - H, sH = SIG(H), sHb = SIG(Hb);
        float2 pH, pHb;
        pH.x  = __shfl_xor_sync(0xffffffffu, v[sH].x,  1);
        pH.y  = __shfl_xor_sync(0xffffffffu, v[sH].y,  1);
        pHb.x = __shfl_xor_sync(0xffffffffu, v[sHb].x, 1);
        pHb.y = __shfl_xor_sync(0xffffffffu, v[sHb].y, 1);
        if (L >= 2){
            const float4 w1 = *(const float4*)(cwb + (size_t)(H  * 33 + k) * CC * 2);
            const float4 w2 = *(const float4*)(cwb + (size_t)(Hb * 33 + k) * CC * 2);
            if (!od){   // col = k (canonical): out1 at (H,k) and (Hb,k)
                const float2 n1v = gate1(v[sH],  pHb, make_float2(w1.x, w1.y), make_float2(w1.z, w1.w));
                const float2 n2v = gate1(v[sHb], pH,  make_float2(w2.x, w2.y), make_float2(w2.z, w2.w));
                v[sH] = n1v; v[sHb] = n2v;
            } else {    // col = 64-k: partner outputs of canonicals (Hb,k) and (H,k)
                const float2 n1v = gate2(pHb, v[sH],  make_float2(w2.x, w2.y), make_float2(w2.z, w2.w));
                const float2 n2v = gate2(pH,  v[sHb], make_float2(w1.x, w1.y), make_float2(w1.z, w1.w));
                v[sH] = n1v; v[sHb] = n2v;
            }
        } else {        // self columns w in {0,32}: symmetrized gate, all local
            const int w = od ? 32 : 0;
            const float4 wA = *(const float4*)(cwb + (size_t)(H  * 33 + w) * CC * 2);
            const float4 wB = *(const float4*)(cwb + (size_t)(Hb * 33 + w) * CC * 2);
            const float2 Ga = make_float2(0.5f*(wA.x + wB.x), 0.5f*(wA.y - wB.y));
            const float2 Gb = make_float2(0.5f*(wA.z + wB.z), 0.5f*(wA.w - wB.w));
            const float2 Z1 = v[sH], Z2 = v[sHb];
            v[sH]  = gate1(Z1, Z2, Ga, Gb);
            v[sHb] = gate2(Z1, Z2, Ga, Gb);
        }
    }
    // self-paired rows H = 0 and H = 32
    #pragma unroll
    for (int e = 0; e < 2; ++e){
        const int H = e ? 32 : 0, sH = SIG(H);
        float2 p0;
        p0.x = __shfl_xor_sync(0xffffffffu, v[sH].x, 1);
        p0.y = __shfl_xor_sync(0xffffffffu, v[sH].y, 1);
        if (L >= 2){
            const float4 w1 = *(const float4*)(cwb + (size_t)(H * 33 + k) * CC * 2);
            const float2 Ga = make_float2(w1.x, w1.y), Gb = make_float2(w1.z, w1.w);
            v[sH] = od ? gate2(p0, v[sH], Ga, Gb) : gate1(v[sH], p0, Ga, Gb);
        } else {
            const int w = od ? 32 : 0;
            const float4 wA = *(const float4*)(cwb + (size_t)(H * 33 + w) * CC * 2);
            const float2 Ga = make_float2(wA.x, 0.0f), Gb = make_float2(wA.z, 0.0f);
            v[sH] = gate1(v[sH], v[sH], Ga, Gb);
        }
    }

    ifft64ds(v);       // back to time-h, natural order
    {   // store tile_N[h][col], col-position permuted by q2(h) = h&31
        const int mc = col >> 1, cb = col & 1;
        #pragma unroll
        for (int h = 0; h < 64; ++h){
            tile[h * 64 + (((mc ^ (h & 31)) << 1) | cb)] = v[h];
        }
    }
    __syncthreads();

    // ---- Phase C: inverse row FFT (thread L = row L), smem -> regs -> gmem ----
    {
        const float4* t4 = (const float4*)tile;
        const int q = L & 31;
        #pragma unroll
        for (int m = 0; m < 32; ++m){
            const float4 f = t4[L * 32 + (m ^ q)];
            v[2*m]   = make_float2(f.x, f.y);
            v[2*m+1] = make_float2(f.z, f.w);
        }
    }
    fft64r<1>(v);      // inverse (unnormalized), x[n] at slot SIG(n)

    float4* oa4 = (float4*)(out + ((size_t)(b * CC + c0)) * 4096);
    float4* ob4 = oa4 + 1024;
    #pragma unroll
    for (int a = 0; a < 16; ++a){
        const int n0 = 4 * a;
        oa4[L * 16 + a] = make_float4(v[SIG(n0)].x, v[SIG(n0+1)].x,
                                      v[SIG(n0+2)].x, v[SIG(n0+3)].x);
        ob4[L * 16 + a] = make_float4(v[SIG(n0)].y, v[SIG(n0+1)].y,
                                      v[SIG(n0+2)].y, v[SIG(n0+3)].y);
    }
}

extern "C" void kernel_launch(void* const* d_in, const int* in_sizes, int n_in,
                              void* d_out, int out_size){
    const float* x  = (const float*)d_in[0];
    const float* cw = (const float*)d_in[1];
    float* out = (float*)d_out;
    dim3 grid(CC / 2, 64);   // (384 channel-pairs, 64 batches)
    sgn_kernel<<<grid, 64>>>(x, cw, out);
}

// round 15
// speedup vs baseline: 1.4348x; 1.4348x over previous
#include <cuda_runtime.h>

// SpectralGatingNetwork: y = irfft2(rfft2(x, ortho) * wc, ortho)
// x: (64, 768, 64, 64) f32; complex_weight: (64, 33, 768, 2) f32; out like x.
//
// R1 architecture (256 threads, octet-parallel shuffle FFTs, 48-reg class)
// with: (a) prep kernel that re-lays weights [cpair][w*64+h] with edge
// symmetrization and ortho scale folded in (coalesced gate loads);
// (b) fused fwd-col + gate + inv-col pass, one column per octet, Hermitian
// partners exchanged between adjacent octets via width-16 shuffles
// (self-columns 0/32 via width-8 in-octet shuffles on warp 0);
// (c) no internal barrier in the fused pass (exclusive column ownership).

#define CC 768

// Prepared gate weights: [cpair=384][w=0..32][h=0..63] float4 = (Ga, Gb),
// scale 1/8192 folded, edge columns (w=0,32) pre-symmetrized.
__device__ float4 g_wt[384 * 33 * 64];

__device__ __forceinline__ float2 cadd(float2 a, float2 b){ return make_float2(a.x+b.x, a.y+b.y); }
__device__ __forceinline__ float2 csub(float2 a, float2 b){ return make_float2(a.x-b.x, a.y-b.y); }
__device__ __forceinline__ float2 cmul(float2 a, float2 b){
    return make_float2(fmaf(a.x, b.x, -a.y*b.y), fmaf(a.x, b.y, a.y*b.x));
}
template<int S>
__device__ __forceinline__ float2 mul_iS(float2 a){
    return (S > 0) ? make_float2(-a.y, a.x) : make_float2(a.y, -a.x);
}

template<int S>
__device__ __forceinline__ void dft8(float2 a[8]){
    const float r  = 0.70710678118654752440f;
    const float sf = (float)S;
    float2 e0 = cadd(a[0], a[4]), e1 = csub(a[0], a[4]);
    float2 e2 = cadd(a[2], a[6]), e3 = mul_iS<S>(csub(a[2], a[6]));
    float2 E0 = cadd(e0, e2), E2 = csub(e0, e2);
    float2 E1 = cadd(e1, e3), E3 = csub(e1, e3);
    float2 o0 = cadd(a[1], a[5]), o1 = csub(a[1], a[5]);
    float2 o2 = cadd(a[3], a[7]), o3 = mul_iS<S>(csub(a[3], a[7]));
    float2 O0 = cadd(o0, o2), O2 = csub(o0, o2);
    float2 O1 = cadd(o1, o3), O3 = csub(o1, o3);
    float2 t1 = make_float2(r * (O1.x - sf * O1.y), r * (O1.y + sf * O1.x));
    float2 t2 = mul_iS<S>(O2);
    float2 t3 = make_float2(-r * (O3.x + sf * O3.y), r * (sf * O3.x - O3.y));
    a[0] = cadd(E0, O0); a[4] = csub(E0, O0);
    a[1] = cadd(E1, t1); a[5] = csub(E1, t1);
    a[2] = cadd(E2, t2); a[6] = csub(E2, t2);
    a[3] = cadd(E3, t3); a[7] = csub(E3, t3);
}

__device__ __forceinline__ void transpose8(float2 a[8], int t){
    #pragma unroll
    for (int m = 1; m < 8; m <<= 1){
        bool hi = (t & m) != 0;
        #pragma unroll
        for (int j0 = 0; j0 < 8; ++j0){
            if ((j0 & m) == 0){
                const int j1 = j0 | m;
                float2 send = hi ? a[j0] : a[j1];
                float2 rcv;
                rcv.x = __shfl_xor_sync(0xffffffffu, send.x, m);
                rcv.y = __shfl_xor_sync(0xffffffffu, send.y, m);
                if (hi) a[j0] = rcv; else a[j1] = rcv;
            }
        }
    }
}

// 64-pt DFT across 8 lanes (t = lane%8). Input a[j] = x[t+8j]; output
// a[j] = X[8j+t].
template<int S>
__device__ __forceinline__ void fft64(float2 a[8], int t){
    dft8<S>(a);
    float sn, cs;
    sincospif((float)(S * t) * (1.0f / 32.0f), &sn, &cs);
    float2 wb = make_float2(cs, sn);
    float2 tw = wb;
    #pragma unroll
    for (int k = 1; k < 8; ++k){
        a[k] = cmul(a[k], tw);
        tw   = cmul(tw, wb);
    }
    transpose8(a, t);
    dft8<S>(a);
}

// Hermitian-split gate (scale folded into Ga/Gb).
// Z1 = canonical-point value, Z2 = partner-point value.
__device__ __forceinline__ float2 gate1(float2 Z1, float2 Z2, float2 Ga, float2 Gb){
    const float2 A  = make_float2(Z1.x + Z2.x, Z1.y - Z2.y);
    const float2 Bv = make_float2(Z1.y + Z2.y, Z2.x - Z1.x);
    const float2 P = cmul(A, Ga), Q = cmul(Bv, Gb);
    return make_float2(P.x - Q.y, P.y + Q.x);   // output at canonical point
}
__device__ __forceinline__ float2 gate2(float2 Z1, float2 Z2, float2 Ga, float2 Gb){
    const float2 A  = make_float2(Z1.x + Z2.x, Z1.y - Z2.y);
    const float2 Bv = make_float2(Z1.y + Z2.y, Z2.x - Z1.x);
    const float2 P = cmul(A, Ga), Q = cmul(Bv, Gb);
    return make_float2(P.x + Q.y, Q.x - P.y);   // output at partner point
}

// Build the "send" registers for the h-reversal exchange: receiver slot j
// must get the sender's value at h-slot matching H -> (64-H)&63.
__device__ __forceinline__ void build_send(const float2 a[8], float2 s[8], int t){
    if (t == 0){
        #pragma unroll
        for (int j = 0; j < 8; ++j) s[j] = a[(8 - j) & 7];
    } else {
        #pragma unroll
        for (int j = 0; j < 8; ++j) s[j] = a[7 - j];
    }
}

// Cross-octet gate: octet pair (o1=0 holds col c, o1=1 holds col 64-c).
template<unsigned MASK>
__device__ __forceinline__ void cross_gate(float2 a[8], const float2 s[8],
                                           int t, int o1,
                                           const float4* __restrict__ wtp, int c){
    const int src = ((o1 ^ 1) << 3) | ((8 - t) & 7);
    #pragma unroll
    for (int j = 0; j < 8; ++j){
        float2 pv;
        pv.x = __shfl_sync(MASK, s[j].x, src, 16);
        pv.y = __shfl_sync(MASK, s[j].y, src, 16);
        const int H = 8 * j + t;
        if (!o1){
            const float4 W = wtp[c * 64 + H];
            a[j] = gate1(a[j], pv, make_float2(W.x, W.y), make_float2(W.z, W.w));
        } else {
            const float4 W = wtp[c * 64 + ((64 - H) & 63)];
            a[j] = gate2(pv, a[j], make_float2(W.x, W.y), make_float2(W.z, W.w));
        }
    }
}

// Self-column gate (w in {0,32}): partner is within the same octet.
__device__ __forceinline__ void self_gate(float2 a[8], const float2 s[8],
                                          int t, const float4* __restrict__ wtp,
                                          int col){
    const int src = (8 - t) & 7;
    #pragma unroll
    for (int j = 0; j < 8; ++j){
        float2 pv;
        pv.x = __shfl_sync(0x0000FFFFu, s[j].x, src, 8);
        pv.y = __shfl_sync(0x0000FFFFu, s[j].y, src, 8);
        const int H = 8 * j + t;
        const float4 W = wtp[col * 64 + H];
        a[j] = gate1(a[j], pv, make_float2(W.x, W.y), make_float2(W.z, W.w));
    }
}

__device__ __forceinline__ int sidx(int h, int w){
    return h * 64 + (w ^ (9 * (h & 7)));
}

// ---- prep: transpose + symmetrize + scale weights ----
__global__ void __launch_bounds__(256)
prep_wt_kernel(const float* __restrict__ cw){
    const int cp = blockIdx.x;            // 0..383
    const int c0 = cp * 2;
    for (int i = threadIdx.x; i < 33 * 64; i += 256){
        const int w = i >> 6;             // 0..32
        const int h = i & 63;             // 0..63
        float4 r = *reinterpret_cast<const float4*>(
            cw + ((size_t)(h * 33 + w) * CC + c0) * 2);
        if (w == 0 || w == 32){
            const int hb = (64 - h) & 63;
            const float4 wB = *reinterpret_cast<const float4*>(
                cw + ((size_t)(hb * 33 + w) * CC + c0) * 2);
            r = make_float4(0.5f * (r.x + wB.x), 0.5f * (r.y - wB.y),
                            0.5f * (r.z + wB.z), 0.5f * (r.w - wB.w));
        }
        const float sc = 1.0f / 8192.0f;
        g_wt[cp * 2112 + i] = make_float4(r.x * sc, r.y * sc, r.z * sc, r.w * sc);
    }
}

__global__ void __launch_bounds__(256, 4)
sgn_kernel(const float* __restrict__ x, float* __restrict__ out){
    __shared__ float2 tile[64 * 64];

    const int tid = threadIdx.x;
    const int t   = tid & 7;        // lane-in-octet
    const int g   = tid >> 3;       // octet 0..31
    const int cpair = blockIdx.x;
    const int b     = blockIdx.y;
    const int c0    = cpair * 2;

    const float* xa = x + ((size_t)(b * CC + c0)) * 4096;
    const float* xb = xa + 4096;

    // ---- forward row FFTs (gmem -> smem) ----
    #pragma unroll
    for (int it = 0; it < 2; ++it){
        const int row = g + 32 * it;
        float2 a[8];
        #pragma unroll
        for (int j = 0; j < 8; ++j){
            const int w = t + 8 * j;
            a[j] = make_float2(xa[row * 64 + w], xb[row * 64 + w]);
        }
        fft64<-1>(a, t);
        #pragma unroll
        for (int j = 0; j < 8; ++j) tile[sidx(row, t + 8 * j)] = a[j];
    }
    __syncthreads();

    // ---- fused: fwd col FFT + gate + inv col FFT ----
    // Pair p = (g>>1) + 16*it; p==0 -> self cols (0,32); else (p, 64-p).
    // Column ownership is exclusive per (octet,it): no internal barrier.
    {
        const int wpid = tid >> 5;
        const int o1   = (g & 1);
        const float4* wtp = g_wt + (size_t)cpair * 2112;
        #pragma unroll
        for (int it = 0; it < 2; ++it){
            const int p   = (g >> 1) + 16 * it;
            const int col = (p == 0) ? (o1 ? 32 : 0) : (o1 ? 64 - p : p);
            const int sw  = col ^ (9 * t);   // sidx(t+8j, col) = (t+8j)*64 + sw

            float2 a[8];
            #pragma unroll
            for (int j = 0; j < 8; ++j) a[j] = tile[(t + 8 * j) * 64 + sw];
            fft64<-1>(a, t);                 // a[j] = Z[8j+t, col]

            float2 s[8];
            build_send(a, s, t);

            if (it == 0 && wpid == 0){
                if ((tid & 16) == 0) self_gate(a, s, t, wtp, col);
                else                 cross_gate<0xFFFF0000u>(a, s, t, o1, wtp, p);
            } else {
                cross_gate<0xFFFFFFFFu>(a, s, t, o1, wtp, p);
            }

            fft64<1>(a, t);                  // inverse column FFT
            #pragma unroll
            for (int j = 0; j < 8; ++j) tile[(t + 8 * j) * 64 + sw] = a[j];
        }
    }
    __syncthreads();

    // ---- inverse row FFTs (smem -> gmem) ----
    float* oa = out + ((size_t)(b * CC + c0)) * 4096;
    float* ob = oa + 4096;
    #pragma unroll
    for (int it = 0; it < 2; ++it){
        const int row = g + 32 * it;
        float2 a[8];
        #pragma unroll
        for (int j = 0; j < 8; ++j) a[j] = tile[sidx(row, t + 8 * j)];
        fft64<1>(a, t);
        #pragma unroll
        for (int j = 0; j < 8; ++j){
            const int w = 8 * j + t;
            oa[row * 64 + w] = a[j].x;
            ob[row * 64 + w] = a[j].y;
        }
    }
}

extern "C" void kernel_launch(void* const* d_in, const int* in_sizes, int n_in,
                              void* d_out, int out_size){
    const float* x  = (const float*)d_in[0];
    const float* cw = (const float*)d_in[1];
    float* out = (float*)d_out;
    prep_wt_kernel<<<384, 256>>>(cw);
    dim3 grid(CC / 2, 64);
    sgn_kernel<<<grid, 256>>>(x, out);
}